// round 4
// baseline (speedup 1.0000x reference)
#include <cuda_runtime.h>
#include <math.h>

// Problem constants
#define BB    8
#define AA    512
#define NBH   64
#define FD    128
#define GD    50
#define NSTR  132
#define PSTR  132
#define FSTR  52

typedef unsigned long long u64;

__device__ __forceinline__ void fma2(u64 &d, u64 a, u64 b) {
    asm("fma.rn.f32x2 %0, %1, %2, %0;" : "+l"(d) : "l"(a), "l"(b));
}
__device__ __forceinline__ u64 pk2(float lo, float hi) {
    u64 r; asm("mov.b64 %0, {%1, %2};" : "=l"(r) : "f"(lo), "f"(hi)); return r;
}
__device__ __forceinline__ float2 upk2(u64 v) {
    float2 t; asm("mov.b64 {%0, %1}, %2;" : "=f"(t.x), "=f"(t.y) : "l"(v)); return t;
}
__device__ __forceinline__ u64 mul2_(u64 a, u64 b) {
    u64 r; asm("mul.rn.f32x2 %0, %1, %2;" : "=l"(r) : "l"(a), "l"(b)); return r;
}
__device__ __forceinline__ u64 add2_(u64 a, u64 b) {
    u64 r; asm("add.rn.f32x2 %0, %1, %2;" : "=l"(r) : "l"(a), "l"(b)); return r;
}

// scratch (device globals: allowed; no allocation)
__device__ float g_p[BB * AA * 1024];   // p[a][h][j]
__device__ float g_u[BB * AA * 1024];   // u[a][h][j]
__device__ int g_mask_u8;

// Detect 1-byte bool vs 4-byte int mask (deterministic).
__global__ void detect_mask_kernel(const unsigned char* __restrict__ m) {
    __shared__ int found;
    if (threadIdx.x == 0) found = 0;
    __syncthreads();
    int acc = 0;
    for (int i = threadIdx.x * 4 + 1; i < 8192; i += blockDim.x * 4)
        if (m[i]) acc = 1;
    if (acc) atomicOr(&found, 1);
    __syncthreads();
    if (threadIdx.x == 0) g_mask_u8 = found;
}

// ---------------------------------------------------------------------------
// K1: p[a][h][j] = sum_d q[a][h*16+d] * Wk[j][h*16+d],  q = x @ Wq
// 32 atoms per block, grid 128.
// ---------------------------------------------------------------------------
__global__ __launch_bounds__(256)
void k1_kernel(const float* __restrict__ x,
               const float* __restrict__ Wq,
               const float* __restrict__ Wk)
{
    __shared__ __align__(16) float s_x[32 * FD];
    __shared__ __align__(16) float s_q[32 * FD];
    __shared__ __align__(16) float s_wk[FD * 18];

    const int tid = threadIdx.x;
    const int a0  = blockIdx.x * 32;

    for (int i = tid; i < 1024; i += 256)
        ((float4*)s_x)[i] = ((const float4*)(x + (size_t)a0 * FD))[i];
    __syncthreads();

    // q tile: thread -> (at, at+16) x f0..f0+8
    {
        const int ft = tid & 15, at = tid >> 4;
        const float* xr0 = s_x + at * FD;
        const float* xr1 = s_x + (at + 16) * FD;
        u64 acc0[4] = {0,0,0,0}, acc1[4] = {0,0,0,0};
        for (int j = 0; j < FD; ++j) {
            ulonglong2 wA = *(const ulonglong2*)(Wq + j * FD + ft * 8);
            ulonglong2 wB = *(const ulonglong2*)(Wq + j * FD + ft * 8 + 4);
            u64 x0 = pk2(xr0[j], xr0[j]);
            u64 x1 = pk2(xr1[j], xr1[j]);
            fma2(acc0[0], x0, wA.x); fma2(acc0[1], x0, wA.y);
            fma2(acc0[2], x0, wB.x); fma2(acc0[3], x0, wB.y);
            fma2(acc1[0], x1, wA.x); fma2(acc1[1], x1, wA.y);
            fma2(acc1[2], x1, wB.x); fma2(acc1[3], x1, wB.y);
        }
        ulonglong2 rA, rB;
        rA.x = acc0[0]; rA.y = acc0[1]; rB.x = acc0[2]; rB.y = acc0[3];
        *(ulonglong2*)(s_q + at * FD + ft * 8)     = rA;
        *(ulonglong2*)(s_q + at * FD + ft * 8 + 4) = rB;
        rA.x = acc1[0]; rA.y = acc1[1]; rB.x = acc1[2]; rB.y = acc1[3];
        *(ulonglong2*)(s_q + (at + 16) * FD + ft * 8)     = rA;
        *(ulonglong2*)(s_q + (at + 16) * FD + ft * 8 + 4) = rB;
    }
    __syncthreads();

    const int a = tid >> 3, jb = tid & 7;
    for (int h = 0; h < 8; ++h) {
        if (h) __syncthreads();    // protect s_wk overwrite
        {
            const int j = tid >> 1, d0 = (tid & 1) * 8;
            const u64* src = (const u64*)(Wk + j * FD + h * 16 + d0);
            u64* dst = (u64*)(s_wk + j * 18 + d0);
            dst[0] = src[0]; dst[1] = src[1]; dst[2] = src[2]; dst[3] = src[3];
        }
        __syncthreads();
        u64 q2[8];
        const float* qrow = s_q + a * FD + h * 16;
        #pragma unroll
        for (int d = 0; d < 8; ++d) q2[d] = *(const u64*)(qrow + 2 * d);
        float* pd = g_p + (size_t)(a0 + a) * 1024 + h * FD + jb;
        #pragma unroll 4
        for (int jj = 0; jj < 16; ++jj) {
            const u64* wk2 = (const u64*)(s_wk + (jb + 8 * jj) * 18);
            u64 acc = 0ull;
            #pragma unroll
            for (int d = 0; d < 8; ++d) fma2(acc, q2[d], wk2[d]);
            float2 rr = upk2(acc);
            pd[8 * jj] = rr.x + rr.y;
        }
    }
}

// ---------------------------------------------------------------------------
// K2: per-atom hot kernel. filter GEMM + gather + scores + softmax + u.
// ---------------------------------------------------------------------------
__global__ __launch_bounds__(256, 4)
void k2_kernel(const float* __restrict__ x,
               const float* __restrict__ r_ij,
               const float* __restrict__ f_ij,
               const float* __restrict__ Wf,
               const float* __restrict__ bfilt,
               const int*   __restrict__ nbr,
               const void*  __restrict__ maskp)
{
    __shared__ __align__(16) float s_nbh[NBH * NSTR];  // 33.8 KB
    __shared__ __align__(16) float s_p[8 * PSTR];      // 4.2 KB
    __shared__ __align__(16) float s_un[NBH * FSTR];   // 13.3 KB: fij | sc
    __shared__ float s_C[NBH];
    __shared__ int   s_nb[NBH];
    __shared__ int   s_mk[NBH];

    float* const s_fij = s_un;
    float* const s_sc  = s_un;   // alias: used only after s_fij is dead

    const int tid  = threadIdx.x;
    const int atom = blockIdx.x;
    const int b    = atom >> 9;
    const float* xb  = x + (size_t)b * (AA * FD);
    const size_t an  = (size_t)atom * NBH;
    const int u8 = g_mask_u8;

    // ---- P0: stage p, f_ij (float2), r/nbr/mask ----
    {
        float4 pv = ((const float4*)(g_p + (size_t)atom * 1024))[tid];
        const int i = 4 * tid, h = i >> 7, j = i & 127;
        *(float4*)(s_p + h * PSTR + j) = pv;
    }
    {
        const float2* fsrc = (const float2*)(f_ij + an * GD);
        for (int i = tid; i < NBH * GD / 2; i += 256) {
            int r = i / 25, c2 = i - r * 25;
            *(float2*)(s_fij + r * FSTR + c2 * 2) = fsrc[i];
        }
    }
    if (tid >= 128 && tid < 192) {
        int n = tid - 128;
        float r = r_ij[an + n];
        s_C[n]  = (r < 5.0f) ? 0.5f * (cospif(r * 0.2f) + 1.0f) : 0.0f;
        s_nb[n] = nbr[an + n];
        int mv;
        if (u8) mv = ((const unsigned char*)maskp)[an + n];
        else    mv = ((const int*)maskp)[an + n];
        s_mk[n] = (mv != 0);
    }
    __syncthreads();

    // ---- P2b: filter GEMM (64x128x50) + cutoff + gather -> s_nbh ----
    {
        const int ft = tid & 15, nt = tid >> 4;
        const int f0 = ft * 8, n0 = nt * 4;
        u64 acc[4][4];
        {
            ulonglong2 bA = *(const ulonglong2*)(bfilt + f0);
            ulonglong2 bB = *(const ulonglong2*)(bfilt + f0 + 4);
            #pragma unroll
            for (int i = 0; i < 4; ++i) {
                acc[i][0] = bA.x; acc[i][1] = bA.y;
                acc[i][2] = bB.x; acc[i][3] = bB.y;
            }
        }
        const float* fr = s_fij + n0 * FSTR;
        for (int g = 0; g < GD; g += 2) {
            u64 av[4];
            #pragma unroll
            for (int i = 0; i < 4; ++i) av[i] = *(const u64*)(fr + i * FSTR + g);
            #pragma unroll
            for (int s = 0; s < 2; ++s) {
                const int gg = g + s;
                ulonglong2 wA = *(const ulonglong2*)(Wf + gg * FD + f0);
                ulonglong2 wB = *(const ulonglong2*)(Wf + gg * FD + f0 + 4);
                #pragma unroll
                for (int i = 0; i < 4; ++i) {
                    float2 t = upk2(av[i]);
                    float aval = s ? t.y : t.x;
                    u64 a2 = pk2(aval, aval);
                    fma2(acc[i][0], a2, wA.x);
                    fma2(acc[i][1], a2, wA.y);
                    fma2(acc[i][2], a2, wB.x);
                    fma2(acc[i][3], a2, wB.y);
                }
            }
        }
        #pragma unroll
        for (int i = 0; i < 4; ++i) {
            const int n = n0 + i;
            const float c = s_C[n];
            const u64 c2 = pk2(c, c);
            const float* xg = xb + (size_t)s_nb[n] * FD + f0;
            ulonglong2 gA = *(const ulonglong2*)(xg);
            ulonglong2 gB = *(const ulonglong2*)(xg + 4);
            ulonglong2 rA, rB;
            rA.x = mul2_(mul2_(acc[i][0], gA.x), c2);
            rA.y = mul2_(mul2_(acc[i][1], gA.y), c2);
            rB.x = mul2_(mul2_(acc[i][2], gB.x), c2);
            rB.y = mul2_(mul2_(acc[i][3], gB.y), c2);
            *(ulonglong2*)(s_nbh + n * NSTR + f0)     = rA;
            *(ulonglong2*)(s_nbh + n * NSTR + f0 + 4) = rB;
        }
    }
    __syncthreads();

    // ---- P3: scores[h][n], masked (s_fij now dead -> s_sc alias OK) ----
    {
        const int n = tid & 63, hp = tid >> 6;
        const float* row = s_nbh + n * NSTR;
        const float* pa  = s_p + hp * PSTR;
        const float* pb  = s_p + (hp + 4) * PSTR;
        u64 A0 = 0ull, A1 = 0ull, B0 = 0ull, B1 = 0ull;
        #pragma unroll 4
        for (int j = 0; j < FD; j += 8) {
            ulonglong2 v0 = *(const ulonglong2*)(row + j);
            ulonglong2 v1 = *(const ulonglong2*)(row + j + 4);
            ulonglong2 qa0 = *(const ulonglong2*)(pa + j);
            ulonglong2 qa1 = *(const ulonglong2*)(pa + j + 4);
            ulonglong2 qb0 = *(const ulonglong2*)(pb + j);
            ulonglong2 qb1 = *(const ulonglong2*)(pb + j + 4);
            fma2(A0, v0.x, qa0.x); fma2(A1, v0.y, qa0.y);
            fma2(A0, v1.x, qa1.x); fma2(A1, v1.y, qa1.y);
            fma2(B0, v0.x, qb0.x); fma2(B1, v0.y, qb0.y);
            fma2(B0, v1.x, qb1.x); fma2(B1, v1.y, qb1.y);
        }
        float2 a0 = upk2(A0), a1 = upk2(A1), b0 = upk2(B0), b1 = upk2(B1);
        float sa = (a0.x + a0.y) + (a1.x + a1.y);
        float sb = (b0.x + b0.y) + (b1.x + b1.y);
        const bool m = (s_mk[n] != 0);
        s_sc[hp * 64 + n]       = m ? sa * 0.25f : -1e9f;
        s_sc[(hp + 4) * 64 + n] = m ? sb * 0.25f : -1e9f;
    }
    __syncthreads();

    // ---- P4: softmax, one warp per head ----
    {
        const int h = tid >> 5, lane = tid & 31;
        float* sc = s_sc + h * 64;
        float v0 = sc[lane], v1 = sc[lane + 32];
        float mx = fmaxf(v0, v1);
        #pragma unroll
        for (int o = 16; o > 0; o >>= 1)
            mx = fmaxf(mx, __shfl_xor_sync(0xffffffffu, mx, o));
        float e0 = __expf(v0 - mx), e1 = __expf(v1 - mx);
        float s = e0 + e1;
        #pragma unroll
        for (int o = 16; o > 0; o >>= 1)
            s += __shfl_xor_sync(0xffffffffu, s, o);
        float inv = 1.0f / s;
        sc[lane] = e0 * inv;
        sc[lane + 32] = e1 * inv;
    }
    __syncthreads();

    // ---- P5: u[h][j] -> g_u ----
    {
        const int h = tid >> 5, lane = tid & 31;
        const float* at = s_sc + h * 64;
        u64 a0 = 0ull, a1 = 0ull;
        #pragma unroll 4
        for (int n = 0; n < NBH; ++n) {
            u64 av = pk2(at[n], at[n]);
            ulonglong2 v = *(const ulonglong2*)(s_nbh + n * NSTR + lane * 4);
            fma2(a0, av, v.x);
            fma2(a1, av, v.y);
        }
        ulonglong2 r; r.x = a0; r.y = a1;
        *(ulonglong2*)(g_u + (size_t)atom * 1024 + h * FD + lane * 4) = r;
    }
}

// ---------------------------------------------------------------------------
// K3: msg = blockdiag(u) @ Wv ; out = x + msg @ Wo + bo. 32 atoms/block.
// ---------------------------------------------------------------------------
__global__ __launch_bounds__(256)
void k3_kernel(const float* __restrict__ x,
               const float* __restrict__ Wv,
               const float* __restrict__ Wo,
               const float* __restrict__ bo,
               float*       __restrict__ out)
{
    __shared__ __align__(16) float s_msg[32 * FD];

    const int tid = threadIdx.x;
    const int a0  = blockIdx.x * 32;
    const int ft = tid & 15, at = tid >> 4;
    const int m0 = ft * 8;

    // phase A: msg[a][m0..+8] for a = at, at+16
    {
        const int h = m0 >> 4;
        const float* uA = g_u + (size_t)(a0 + at) * 1024 + h * FD;
        const float* uB = uA + (size_t)16 * 1024;
        u64 acc0[4] = {0,0,0,0}, acc1[4] = {0,0,0,0};
        for (int j = 0; j < FD; ++j) {
            ulonglong2 wA = *(const ulonglong2*)(Wv + j * FD + m0);
            ulonglong2 wB = *(const ulonglong2*)(Wv + j * FD + m0 + 4);
            u64 va = pk2(uA[j], uA[j]);
            u64 vb = pk2(uB[j], uB[j]);
            fma2(acc0[0], va, wA.x); fma2(acc0[1], va, wA.y);
            fma2(acc0[2], va, wB.x); fma2(acc0[3], va, wB.y);
            fma2(acc1[0], vb, wA.x); fma2(acc1[1], vb, wA.y);
            fma2(acc1[2], vb, wB.x); fma2(acc1[3], vb, wB.y);
        }
        ulonglong2 rA, rB;
        rA.x = acc0[0]; rA.y = acc0[1]; rB.x = acc0[2]; rB.y = acc0[3];
        *(ulonglong2*)(s_msg + at * FD + m0)     = rA;
        *(ulonglong2*)(s_msg + at * FD + m0 + 4) = rB;
        rA.x = acc1[0]; rA.y = acc1[1]; rB.x = acc1[2]; rB.y = acc1[3];
        *(ulonglong2*)(s_msg + (at + 16) * FD + m0)     = rA;
        *(ulonglong2*)(s_msg + (at + 16) * FD + m0 + 4) = rB;
    }
    __syncthreads();

    // phase B: out[a][f0..+8] = x + msg @ Wo + bo
    {
        const int f0 = m0;
        u64 acc0[4], acc1[4];
        {
            ulonglong2 bA = *(const ulonglong2*)(bo + f0);
            ulonglong2 bB = *(const ulonglong2*)(bo + f0 + 4);
            acc0[0] = bA.x; acc0[1] = bA.y; acc0[2] = bB.x; acc0[3] = bB.y;
            acc1[0] = bA.x; acc1[1] = bA.y; acc1[2] = bB.x; acc1[3] = bB.y;
        }
        const float* mA = s_msg + at * FD;
        const float* mB = s_msg + (at + 16) * FD;
        for (int m = 0; m < FD; ++m) {
            ulonglong2 wA = *(const ulonglong2*)(Wo + m * FD + f0);
            ulonglong2 wB = *(const ulonglong2*)(Wo + m * FD + f0 + 4);
            u64 va = pk2(mA[m], mA[m]);
            u64 vb = pk2(mB[m], mB[m]);
            fma2(acc0[0], va, wA.x); fma2(acc0[1], va, wA.y);
            fma2(acc0[2], va, wB.x); fma2(acc0[3], va, wB.y);
            fma2(acc1[0], vb, wA.x); fma2(acc1[1], vb, wA.y);
            fma2(acc1[2], vb, wB.x); fma2(acc1[3], vb, wB.y);
        }
        const float* xA = x + (size_t)(a0 + at) * FD + f0;
        const float* xB = x + (size_t)(a0 + at + 16) * FD + f0;
        ulonglong2 xa0 = *(const ulonglong2*)(xA);
        ulonglong2 xa1 = *(const ulonglong2*)(xA + 4);
        ulonglong2 xb0 = *(const ulonglong2*)(xB);
        ulonglong2 xb1 = *(const ulonglong2*)(xB + 4);
        ulonglong2 rA, rB;
        rA.x = add2_(acc0[0], xa0.x); rA.y = add2_(acc0[1], xa0.y);
        rB.x = add2_(acc0[2], xa1.x); rB.y = add2_(acc0[3], xa1.y);
        *(ulonglong2*)(out + (size_t)(a0 + at) * FD + f0)     = rA;
        *(ulonglong2*)(out + (size_t)(a0 + at) * FD + f0 + 4) = rB;
        rA.x = add2_(acc1[0], xb0.x); rA.y = add2_(acc1[1], xb0.y);
        rB.x = add2_(acc1[2], xb1.x); rB.y = add2_(acc1[3], xb1.y);
        *(ulonglong2*)(out + (size_t)(a0 + at + 16) * FD + f0)     = rA;
        *(ulonglong2*)(out + (size_t)(a0 + at + 16) * FD + f0 + 4) = rB;
    }
}

extern "C" void kernel_launch(void* const* d_in, const int* in_sizes, int n_in,
                              void* d_out, int out_size)
{
    // metadata order: e, x, t, r_ij, f_ij, W_filt, b_filt, Wq, Wk, Wv, Wo, bo,
    //                 neighbors, neighbor_mask     (e and t are unused)
    const float* x    = (const float*)d_in[1];
    const float* r    = (const float*)d_in[3];
    const float* fij  = (const float*)d_in[4];
    const float* Wf   = (const float*)d_in[5];
    const float* bf   = (const float*)d_in[6];
    const float* Wq   = (const float*)d_in[7];
    const float* Wk   = (const float*)d_in[8];
    const float* Wv   = (const float*)d_in[9];
    const float* Wo   = (const float*)d_in[10];
    const float* bo   = (const float*)d_in[11];
    const int*   nbr  = (const int*)d_in[12];
    const void*  mk   = d_in[13];

    detect_mask_kernel<<<1, 256>>>((const unsigned char*)mk);
    k1_kernel<<<128, 256>>>(x, Wq, Wk);
    k2_kernel<<<BB * AA, 256>>>(x, r, fij, Wf, bf, nbr, mk);
    k3_kernel<<<128, 256>>>(x, Wv, Wo, bo, (float*)d_out);
}